// round 17
// baseline (speedup 1.0000x reference)
#include <cuda_runtime.h>
#include <stdint.h>

#define NSLOTS 4096
#define TPB 1024
#define PT 4            // NSLOTS / TPB
#define NW 32           // warps per block
#define KPAD 672
#define EPSF 1e-3f

__global__ __launch_bounds__(TPB) void latent_handler_kernel(
    const float* __restrict__ z_where,
    const float* __restrict__ z_present,
    const float* __restrict__ z_what_loc,
    const float* __restrict__ z_depth_loc,
    const float* __restrict__ neg_priority,
    float* __restrict__ out,
    int B, int K)
{
    __shared__ unsigned long long s_cand[NSLOTS]; // worst-case tie-break store
    __shared__ int s_idxmap[KPAD];                // packed: slot | (present << 15)
    __shared__ int s_wsum[2][NW];
    __shared__ int s_scal[4];

    const int b    = blockIdx.x;
    const int tid  = threadIdx.x;
    const int lane = tid & 31;
    const int warp = tid >> 5;
    const int base = tid * PT;

    // ---- load presence + priority; digits & keys stay in registers ----
    int presf[PT], digr[PT];
    unsigned int keyr[PT];
    {
        float4 p = ((const float4*)(z_present    + (size_t)b * NSLOTS))[tid];
        float4 q = ((const float4*)(neg_priority + (size_t)b * NSLOTS))[tid];
        float pv[4] = {p.x, p.y, p.z, p.w};
        float qv[4] = {q.x, q.y, q.z, q.w};
        #pragma unroll
        for (int j = 0; j < PT; j++) {
            bool pres = pv[j] > EPSF;
            presf[j] = pres ? 1 : 0;
            unsigned int bits = __float_as_uint(qv[j]);
            unsigned int msk  = (unsigned int)(((int)bits) >> 31) | 0x80000000u;
            keyr[j] = bits ^ msk;                       // order-preserving uint key
            int d = __float2int_rd(qv[j] * 4096.0f);    // exact ×2^12, monotone
            d = min(4095, max(0, d));
            digr[j] = pres ? 0x7FFF : d;                // present never counted
        }
    }

    // ---- n_present: warp reduce -> buf0 -> all-warps redundant reduce ----
    {
        int c = presf[0] + presf[1] + presf[2] + presf[3];
        c = __reduce_add_sync(0xFFFFFFFFu, c);
        if (lane == 0) s_wsum[0][warp] = c;
        if (tid == 0) s_scal[0] = 0;                    // candidate counter
    }
    __syncthreads();                                    // B0
    int n_present;
    {
        int v = s_wsum[0][lane];
        #pragma unroll
        for (int o = 16; o; o >>= 1) v += __shfl_xor_sync(0xFFFFFFFFu, v, o);
        n_present = v;                                  // identical in all threads
    }
    const int n_neg = K - n_present;

    // ---- ballot binary search over 12-bit digit space ----
    // buffer phase (it+1)&1: iteration 0 writes buf1, so it cannot clobber
    // buf0 while other warps still read it for n_present; each iteration's
    // sync then protects the subsequent reuse of the other buffer.
    int winbin = -1, t_rem = 0, cnt_eq = 0;
    if (n_neg > 0) {
        int lo = 0, hi = 4096, flo = 0, fhi = NSLOTS - n_present;
        #pragma unroll
        for (int it = 0; it < 12; it++) {
            const int buf = (it + 1) & 1;
            int mid = (lo + hi) >> 1;
            int cc = (digr[0] < mid) + (digr[1] < mid) + (digr[2] < mid) + (digr[3] < mid);
            cc = __reduce_add_sync(0xFFFFFFFFu, cc);
            if (lane == 0) s_wsum[buf][warp] = cc;
            __syncthreads();
            int v = s_wsum[buf][lane];
            #pragma unroll
            for (int o = 16; o; o >>= 1) v += __shfl_xor_sync(0xFFFFFFFFu, v, o);
            if (v >= n_neg) { hi = mid; fhi = v; }
            else           { lo = mid; flo = v; }
        }
        winbin = lo;                                    // f(lo) < n_neg <= f(lo+1)
        t_rem  = n_neg - flo;
        cnt_eq = fhi - flo;
    }
    __syncthreads();   // protect last-read buffer before any rewrite below

    const bool need_exact = (winbin >= 0) && (t_rem < cnt_eq);

    // ---- tie-break candidates for the winner bin only (usually ~1-4) ----
    if (need_exact) {                                   // uniform branch
        #pragma unroll
        for (int j = 0; j < PT; j++)
            if (!presf[j] && digr[j] == winbin) {
                int pos = atomicAdd(&s_scal[0], 1);
                s_cand[pos] = ((unsigned long long)keyr[j] << 32) | (unsigned)(base + j);
            }
        __syncthreads();
    }

    // ---- keep decision + compaction scan -> packed idxmap ----
    int keep[PT], local[PT];
    int sum = 0;
    #pragma unroll
    for (int j = 0; j < PT; j++) {
        bool kp;
        if (presf[j]) kp = true;
        else if (winbin < 0) kp = false;
        else {
            int d = digr[j];
            if (d < winbin) kp = true;
            else if (d > winbin) kp = false;
            else if (!need_exact) kp = true;
            else {
                unsigned long long my = ((unsigned long long)keyr[j] << 32) | (unsigned)(base + j);
                int r = 0, nc = s_scal[0];
                for (int t = 0; t < nc; t++) r += (s_cand[t] < my);
                kp = (r < t_rem);                       // stable (key, idx) rank
            }
        }
        keep[j] = kp ? 1 : 0;
        local[j] = sum;
        sum += keep[j];
    }
    int ws = sum;
    #pragma unroll
    for (int o = 1; o < 32; o <<= 1) {
        int v = __shfl_up_sync(0xFFFFFFFFu, ws, o);
        if (lane >= o) ws += v;
    }
    if (lane == 31) s_wsum[0][warp] = ws;
    __syncthreads();
    int wbase;
    {
        int v = (lane < warp) ? s_wsum[0][lane] : 0;    // all-warps exclusive base
        #pragma unroll
        for (int o = 16; o; o >>= 1) v += __shfl_xor_sync(0xFFFFFFFFu, v, o);
        wbase = v;
    }
    {
        int tb = wbase + (ws - sum);
        #pragma unroll
        for (int j = 0; j < PT; j++)
            if (keep[j]) {
                int p = tb + local[j];
                if (p < KPAD)
                    s_idxmap[p] = (base + j) | (presf[j] << 15);
            }
    }
    __syncthreads();

    // ---- epilogue (R7-proven): MLP-batched gather + stream ----
    float* out_where = out;                             // [B, K, 4]
    float* out_mod   = out + (size_t)B * K * 4;         // [B, K, 1]
    float* out_what  = out + (size_t)B * K * 5;         // [B, K, 64]
    float* out_depth = out + (size_t)B * K * 69;        // [B, K, 1]

    const float4* zw4 = (const float4*)z_where + (size_t)b * NSLOTS;
    const float*  zd  = z_depth_loc + (size_t)b * NSLOTS;

    for (int p = tid; p < K; p += TPB) {                // K < TPB: 1 iteration
        int e = s_idxmap[p];
        int slot = e & 0xFFF;
        bool pres = (e & 0x8000) != 0;
        float4 w = __ldg(&zw4[slot]);
        float m = fmaxf(w.z, w.w);
        ((float4*)out_where)[(size_t)b * K + p] = make_float4(w.x, w.y, m, m);
        out_mod[(size_t)b * K + p]   = pres ? 1.0f : -1.0f;
        out_depth[(size_t)b * K + p] = pres ? __ldg(&zd[slot]) : 0.0f;
    }

    const float4* wl4 = (const float4*)z_what_loc + (size_t)b * NSLOTS * 16;
    float4* ow4 = (float4*)out_what + (size_t)b * K * 16;
    const int total = K * 16;
    const int c = tid & 15;                             // loop-invariant column
    int i = tid;
    for (; i + 3 * TPB < total; i += 4 * TPB) {         // batches of 4 for MLP
        int e0 = s_idxmap[(i          ) >> 4];
        int e1 = s_idxmap[(i +     TPB) >> 4];
        int e2 = s_idxmap[(i + 2 * TPB) >> 4];
        int e3 = s_idxmap[(i + 3 * TPB) >> 4];
        float4 v0 = make_float4(0.f, 0.f, 0.f, 0.f);
        float4 v1 = v0, v2 = v0, v3 = v0;
        if (e0 & 0x8000) v0 = __ldg(&wl4[(e0 & 0xFFF) * 16 + c]);
        if (e1 & 0x8000) v1 = __ldg(&wl4[(e1 & 0xFFF) * 16 + c]);
        if (e2 & 0x8000) v2 = __ldg(&wl4[(e2 & 0xFFF) * 16 + c]);
        if (e3 & 0x8000) v3 = __ldg(&wl4[(e3 & 0xFFF) * 16 + c]);
        ow4[i          ] = v0;
        ow4[i +     TPB] = v1;
        ow4[i + 2 * TPB] = v2;
        ow4[i + 3 * TPB] = v3;
    }
    for (; i < total; i += TPB) {
        int e = s_idxmap[i >> 4];
        float4 v = make_float4(0.f, 0.f, 0.f, 0.f);
        if (e & 0x8000) v = __ldg(&wl4[(e & 0xFFF) * 16 + c]);
        ow4[i] = v;
    }
}

extern "C" void kernel_launch(void* const* d_in, const int* in_sizes, int n_in,
                              void* d_out, int out_size) {
    const float* z_where      = (const float*)d_in[0];
    const float* z_present    = (const float*)d_in[1];
    const float* z_what_loc   = (const float*)d_in[2];
    // d_in[3] = z_what_scale  (never read)
    const float* z_depth_loc  = (const float*)d_in[4];
    // d_in[5] = z_depth_scale (never read)
    const float* neg_priority = (const float*)d_in[6];

    const int B = in_sizes[6] / NSLOTS;
    const int K = out_size / (B * 70);

    latent_handler_kernel<<<B, TPB>>>(z_where, z_present, z_what_loc,
                                      z_depth_loc, neg_priority,
                                      (float*)d_out, B, K);
}